// round 11
// baseline (speedup 1.0000x reference)
#include <cuda_runtime.h>
#include <cuda_fp16.h>
#include <cstdint>

#define DD 256          // feature dim
#define NP 256          // points per group
#define MAXG 128        // groups
#define TPB 256
#define PERSIST_SM 148  // B300/GB300 SMs (GB300 has 152; 296 CTAs still balanced)

// ---------------------------------------------------------------------------
// Scratch (no cudaMalloc allowed)
// ---------------------------------------------------------------------------
__device__ __half g_xh[MAXG * NP * DD];
__device__ __half g_yh[MAXG * NP * DD];
__device__ float g_xn[MAXG * NP], g_yn[MAXG * NP];
__device__ float g_part[10 * MAXG];

__device__ __forceinline__ uint32_t smem_u32(const void* p) {
    uint32_t a;
    asm("{ .reg .u64 t; cvta.to.shared.u64 t, %1; cvt.u32.u64 %0, t; }"
        : "=r"(a) : "l"(p));
    return a;
}

#define CP_ASYNC16(so, gp) \
    asm volatile("cp.async.cg.shared.global [%0], [%1], 16;" :: "r"(so), "l"(gp))
#define CP_COMMIT() asm volatile("cp.async.commit_group;" ::: "memory")
#define CP_WAIT0()  asm volatile("cp.async.wait_group 0;" ::: "memory")

#define LDSM_X4(r0, r1, r2, r3, addr) \
    asm volatile("ldmatrix.sync.aligned.m8n8.x4.shared.b16 {%0,%1,%2,%3}, [%4];" \
                 : "=r"(r0), "=r"(r1), "=r"(r2), "=r"(r3) : "r"(addr))

#define MMA16816(d, a, b) \
    asm volatile("mma.sync.aligned.m16n8k16.row.col.f32.f16.f16.f32 " \
                 "{%0,%1,%2,%3}, {%4,%5,%6,%7}, {%8,%9}, {%0,%1,%2,%3};" \
                 : "+f"((d)[0]), "+f"((d)[1]), "+f"((d)[2]), "+f"((d)[3]) \
                 : "r"((a)[0]), "r"((a)[1]), "r"((a)[2]), "r"((a)[3]), \
                   "r"((b)[0]), "r"((b)[1]))

// ---------------------------------------------------------------------------
// Pass 1: fp32 -> fp16 + squared norms. Warp per 2 rows (MLP=4 LDG.128/lane).
// ---------------------------------------------------------------------------
__global__ void prep_kernel(const float* __restrict__ x,
                            const float* __restrict__ y, int rows) {
    int pairs = rows >> 1;
    int warp = blockIdx.x * (blockDim.x >> 5) + (threadIdx.x >> 5);
    int lane = threadIdx.x & 31;
    if (warp >= 2 * pairs) return;
    bool isx = warp < pairs;
    int row0 = (isx ? warp : warp - pairs) * 2;
    const float4* src = (const float4*)((isx ? x : y) + (size_t)row0 * DD);
    __half* hd = (isx ? g_xh : g_yh) + (size_t)row0 * DD;

    // front-batch 4 independent LDG.128
    float4 a0 = src[lane];
    float4 a1 = src[lane + 32];
    float4 b0 = src[64 + lane];
    float4 b1 = src[64 + lane + 32];

    float sa = 0.f, sb = 0.f;
    uint2 pk;
    __half2 h01, h23;

    h01 = __floats2half2_rn(a0.x, a0.y); h23 = __floats2half2_rn(a0.z, a0.w);
    pk.x = *(uint32_t*)&h01; pk.y = *(uint32_t*)&h23;
    ((uint2*)hd)[lane] = pk;
    sa += a0.x * a0.x + a0.y * a0.y + a0.z * a0.z + a0.w * a0.w;

    h01 = __floats2half2_rn(a1.x, a1.y); h23 = __floats2half2_rn(a1.z, a1.w);
    pk.x = *(uint32_t*)&h01; pk.y = *(uint32_t*)&h23;
    ((uint2*)hd)[lane + 32] = pk;
    sa += a1.x * a1.x + a1.y * a1.y + a1.z * a1.z + a1.w * a1.w;

    h01 = __floats2half2_rn(b0.x, b0.y); h23 = __floats2half2_rn(b0.z, b0.w);
    pk.x = *(uint32_t*)&h01; pk.y = *(uint32_t*)&h23;
    ((uint2*)hd)[64 + lane] = pk;
    sb += b0.x * b0.x + b0.y * b0.y + b0.z * b0.z + b0.w * b0.w;

    h01 = __floats2half2_rn(b1.x, b1.y); h23 = __floats2half2_rn(b1.z, b1.w);
    pk.x = *(uint32_t*)&h01; pk.y = *(uint32_t*)&h23;
    ((uint2*)hd)[64 + lane + 32] = pk;
    sb += b1.x * b1.x + b1.y * b1.y + b1.z * b1.z + b1.w * b1.w;

#pragma unroll
    for (int o = 16; o; o >>= 1) {
        sa += __shfl_xor_sync(0xffffffffu, sa, o);
        sb += __shfl_xor_sync(0xffffffffu, sb, o);
    }
    if (lane == 0) {
        float* dst = isx ? g_xn : g_yn;
        dst[row0]     = sa;
        dst[row0 + 1] = sb;
    }
}

// ---------------------------------------------------------------------------
// Work-item decode: item -> (group, block) -> operand pointers + weight.
// Per group: 4 XY blocks (w=1), 3 XX, 3 YY (off-diag counted once, w doubled).
// ---------------------------------------------------------------------------
struct Item {
    const __half *Ap, *Bp;
    const float *An, *Bn;
    int t, mi, ni;
    float w;
};
__device__ __forceinline__ Item decode_item(int item) {
    Item it;
    int g = item / 10, blk = item % 10;
    if (blk < 4) { it.t = 0; it.mi = blk >> 1; it.ni = blk & 1; it.w = 1.0f; }
    else {
        int q = blk - 4;
        it.t = 1 + q / 3;
        int r3 = q % 3;
        it.mi = (r3 == 2) ? 1 : 0;
        it.ni = (r3 == 0) ? 0 : 1;
        it.w = (r3 == 1) ? -1.0f : -0.5f;
    }
    const __half* Ag = (it.t == 2) ? g_yh : g_xh;
    const __half* Bg = (it.t == 0) ? g_yh : ((it.t == 1) ? g_xh : g_yh);
    it.An = (it.t == 2) ? g_yn : g_xn;
    it.Bn = (it.t == 0) ? g_yn : ((it.t == 1) ? g_xn : g_yn);
    it.Ap = Ag + ((size_t)g * NP + it.mi * 128) * DD;
    it.Bp = Bg + ((size_t)g * NP + it.ni * 128) * DD;
    it.An += g * NP + it.mi * 128;
    it.Bn += g * NP + it.ni * 128;
    return it;
}

// ---------------------------------------------------------------------------
// Stage loader: 128x64 fp16 A tile + 128x64 B tile, cp.async, xor-swizzled.
// ---------------------------------------------------------------------------
__device__ __forceinline__ void stage_load(uint32_t sa, const __half* Ap,
                                           const __half* Bp, int tid) {
#pragma unroll
    for (int i = 0; i < 4; i++) {
        int e = tid + i * TPB;
        int r = e >> 3, cc = e & 7;
        uint32_t so = sa + (uint32_t)(r * 128 + ((cc ^ (r & 7)) << 4));
        CP_ASYNC16(so, Ap + (size_t)r * DD + cc * 8);
    }
    uint32_t sb = sa + 16384;
#pragma unroll
    for (int i = 0; i < 4; i++) {
        int e = tid + i * TPB;
        int r = e >> 3, cc = e & 7;
        uint32_t so = sb + (uint32_t)(r * 128 + ((cc ^ (r & 7)) << 4));
        CP_ASYNC16(so, Bp + (size_t)r * DD + cc * 8);
    }
}

// ---------------------------------------------------------------------------
// Pass 2: persistent-CTA fp16 HMMA GEMM + fused distance epilogue.
// grid = 2 * #SM; each CTA loops over work items with cross-item prefetch.
// ---------------------------------------------------------------------------
__global__ __launch_bounds__(TPB, 2)
void gemm_kernel(int nitems) {
    extern __shared__ __align__(16) char dsmem[];   // 2 stages x 32KB
    __shared__ float an_s[128], bn_s[128], red[8];

    int tid = threadIdx.x, wid = tid >> 5, lane = tid & 31;
    int wm = (wid & 1) * 64;        // warp M offset (2 warps in M)
    int wn = (wid >> 1) * 32;       // warp N offset (4 warps in N)
    uint32_t s0 = smem_u32(dsmem);

    int item = blockIdx.x;
    if (item >= nitems) return;
    Item cur = decode_item(item);

    // prime the pipeline: first item's stage 0
    stage_load(s0, cur.Ap, cur.Bp, tid);
    CP_COMMIT();

    while (true) {
        int nxt = item + gridDim.x;
        bool has_next = nxt < nitems;
        Item nx;
        if (has_next) nx = decode_item(nxt);

        if (tid < 128) an_s[tid] = cur.An[tid];
        else           bn_s[tid - 128] = cur.Bn[tid - 128];

        float acc[4][4][4];
#pragma unroll
        for (int a = 0; a < 4; a++)
#pragma unroll
            for (int b = 0; b < 4; b++)
#pragma unroll
                for (int c = 0; c < 4; c++) acc[a][b][c] = 0.f;

        for (int kb = 0; kb < 4; kb++) {              // 4 x KT=64
            CP_WAIT0();
            __syncthreads();
            if (kb < 3) {
                stage_load(s0 + ((kb + 1) & 1) * 32768,
                           cur.Ap + (kb + 1) * 64, cur.Bp + (kb + 1) * 64, tid);
                CP_COMMIT();
            } else if (has_next) {
                // cross-item prefetch into stage 0 (read-free since kb=2's sync)
                stage_load(s0, nx.Ap, nx.Bp, tid);
                CP_COMMIT();
            }
            uint32_t ab = s0 + (kb & 1) * 32768;
            uint32_t bb = ab + 16384;

#pragma unroll
            for (int ks = 0; ks < 4; ks++) {          // 4 x k16 per stage
                int k0 = ks * 16;
                uint32_t af[4][4], bf[4][2];
                {
                    int arow = wm + (lane & 15);
                    int accc = (k0 >> 3) + (lane >> 4);
#pragma unroll
                    for (int mt = 0; mt < 4; mt++) {
                        int row = arow + mt * 16;
                        uint32_t ad = ab + (uint32_t)(row * 128 + ((accc ^ (row & 7)) << 4));
                        LDSM_X4(af[mt][0], af[mt][1], af[mt][2], af[mt][3], ad);
                    }
                }
                {
                    int brow0 = wn + (lane & 7) + ((lane >> 4) << 3);
                    int bcc = (k0 >> 3) + ((lane >> 3) & 1);
#pragma unroll
                    for (int p = 0; p < 2; p++) {
                        int row = brow0 + p * 16;
                        uint32_t bd = bb + (uint32_t)(row * 128 + ((bcc ^ (row & 7)) << 4));
                        uint32_t q0, q1, q2, q3;
                        LDSM_X4(q0, q1, q2, q3, bd);
                        bf[2 * p][0] = q0; bf[2 * p][1] = q1;
                        bf[2 * p + 1][0] = q2; bf[2 * p + 1][1] = q3;
                    }
                }
#pragma unroll
                for (int mt = 0; mt < 4; mt++)
#pragma unroll
                    for (int nt = 0; nt < 4; nt++)
                        MMA16816(acc[mt][nt], af[mt], bf[nt]);
            }
        }

        // ---- epilogue: d2 = |a|^2 + |b|^2 - 2 dot; zero exact diagonal (XX/YY)
        bool diagblk = (cur.t != 0) && (cur.mi == cur.ni);
        float sum = 0.f;
#pragma unroll
        for (int mt = 0; mt < 4; mt++) {
            int i0 = wm + mt * 16 + (lane >> 2);
            float an0 = an_s[i0], an1 = an_s[i0 + 8];
#pragma unroll
            for (int nt = 0; nt < 4; nt++) {
                int j0 = wn + nt * 8 + 2 * (lane & 3);
                float bn0 = bn_s[j0], bn1 = bn_s[j0 + 1];
                float* c = acc[mt][nt];
                float d00 = an0 + bn0 - 2.0f * c[0];
                float d01 = an0 + bn1 - 2.0f * c[1];
                float d10 = an1 + bn0 - 2.0f * c[2];
                float d11 = an1 + bn1 - 2.0f * c[3];
                float s00 = sqrtf(fmaxf(d00, 0.f));
                float s01 = sqrtf(fmaxf(d01, 0.f));
                float s10 = sqrtf(fmaxf(d10, 0.f));
                float s11 = sqrtf(fmaxf(d11, 0.f));
                if (diagblk) {
                    if (i0 == j0)         s00 = 0.f;
                    if (i0 == j0 + 1)     s01 = 0.f;
                    if (i0 + 8 == j0)     s10 = 0.f;
                    if (i0 + 8 == j0 + 1) s11 = 0.f;
                }
                sum += s00 + s01 + s10 + s11;
            }
        }

        // ---- deterministic block reduction
#pragma unroll
        for (int o = 16; o; o >>= 1) sum += __shfl_xor_sync(0xffffffffu, sum, o);
        if (lane == 0) red[wid] = sum;
        __syncthreads();
        if (wid == 0) {
            float v = (lane < 8) ? red[lane] : 0.f;
#pragma unroll
            for (int o = 4; o; o >>= 1) v += __shfl_xor_sync(0xffffffffu, v, o);
            if (lane == 0) g_part[item] = cur.w * v;
        }
        __syncthreads();   // protect an_s/bn_s/red before next item overwrites

        if (!has_next) break;
        item = nxt;
        cur = nx;
    }
}

// ---------------------------------------------------------------------------
// Pass 3: deterministic final reduction.
// ---------------------------------------------------------------------------
__global__ void reduce_kernel(float* __restrict__ out, int G) {
    __shared__ float red[16];
    int tid = threadIdx.x;
    float s = 0.f;
    for (int i = tid; i < 10 * G; i += blockDim.x) s += g_part[i];
#pragma unroll
    for (int o = 16; o; o >>= 1) s += __shfl_xor_sync(0xffffffffu, s, o);
    if ((tid & 31) == 0) red[tid >> 5] = s;
    __syncthreads();
    if (tid < 32) {
        float v = (tid < 16) ? red[tid] : 0.f;
#pragma unroll
        for (int o = 8; o; o >>= 1) v += __shfl_xor_sync(0xffffffffu, v, o);
        if (tid == 0) out[0] = v / ((float)NP * (float)NP * (float)G);
    }
}

// ---------------------------------------------------------------------------
extern "C" void kernel_launch(void* const* d_in, const int* in_sizes, int n_in,
                              void* d_out, int out_size) {
    const float* x = (const float*)d_in[0];
    const float* y = (const float*)d_in[1];
    int G = in_sizes[0] / (NP * DD);
    if (G > MAXG) G = MAXG;
    int rows = G * NP;
    int nitems = 10 * G;

    static int smem_set = 0;
    if (!smem_set) {
        cudaFuncSetAttribute(gemm_kernel,
                             cudaFuncAttributeMaxDynamicSharedMemorySize, 65536);
        smem_set = 1;
    }

    int nwarps = rows;                       // warp per 2 rows, x and y sides
    prep_kernel<<<(nwarps + 7) / 8, 256>>>(x, y, rows);
    int grid = 2 * PERSIST_SM;
    if (grid > nitems) grid = nitems;
    gemm_kernel<<<grid, TPB, 65536>>>(nitems);
    reduce_kernel<<<1, 512>>>((float*)d_out, G);
}